// round 14
// baseline (speedup 1.0000x reference)
#include <cuda_runtime.h>
#include <cuda_fp16.h>
#include <cstdint>

// ---------------------------------------------------------------------------
// Problem constants
// ---------------------------------------------------------------------------
constexpr int B_ = 8;
constexpr int N_ = 2048;
constexpr int D_ = 512;
constexpr int M_ = B_ * N_;                    // 16384
constexpr float SCALE = 0.04419417382415922f;  // 1/sqrt(512)

// Unified fp16 GEMM path: CTA tile 128x128, K-chunk 64, 3-stage x 32KB = 96KB,
// 2 CTAs/SM. Stage: A 16KB | B 16KB.
constexpr int S1_STAGE = 32768;
constexpr int OFF_B1 = 16384;
constexpr int SMEM_BYTES = 3 * S1_STAGE;       // 98304

// ---------------------------------------------------------------------------
// Scratch (static __device__: allocation-guard safe; zero-initialized at load)
// ---------------------------------------------------------------------------
__device__ __align__(256) __half g_xf[(size_t)M_ * D_];          // fp16 x
__device__ __align__(256) __half g_wf[(size_t)3 * D_ * D_];      // fp16 Wq|Wk|Wv
__device__ __align__(256) __half g_qf[(size_t)M_ * D_];          // fp16 q
__device__ __align__(256) __half g_kf[(size_t)M_ * D_];          // fp16 k
__device__ __align__(256) __half g_vtf[(size_t)B_ * D_ * N_];    // fp16 V^T [b][d][n]
__device__ __align__(256) __half g_pf[(size_t)B_ * N_ * N_];     // fp16 exp numerators
__device__ __align__(256) float  g_psum[(size_t)B_ * 16 * N_];   // per-ntile row sums
__device__ __align__(256) float  g_cspart[(size_t)B_ * 32 * D_]; // colsum(x) partials
__device__ __align__(256) float  g_mean[(size_t)B_ * D_];        // colmean(V)

// ---------------------------------------------------------------------------
// Helpers
// ---------------------------------------------------------------------------
__device__ __forceinline__ uint32_t smem_u32(const void* p) {
    uint32_t a;
    asm("{ .reg .u64 t; cvta.to.shared.u64 t, %1; cvt.u32.u64 %0, t; }" : "=r"(a) : "l"(p));
    return a;
}
#define SW128(o) ((o) ^ (((o) >> 3) & 0x70))

#define CP16(dst, src) \
    asm volatile("cp.async.cg.shared.global [%0], [%1], 16;" :: "r"(dst), "l"(src) : "memory")
#define CP_COMMIT() asm volatile("cp.async.commit_group;" ::: "memory")
#define CP_WAIT1() asm volatile("cp.async.wait_group 1;" ::: "memory")
#define CP_WAIT0() asm volatile("cp.async.wait_group 0;" ::: "memory")

#define LDSM4(r0, r1, r2, r3, a) \
    asm volatile("ldmatrix.sync.aligned.m8n8.x4.shared.b16 {%0,%1,%2,%3}, [%4];" \
                 : "=r"(r0), "=r"(r1), "=r"(r2), "=r"(r3) : "r"(a))

#define MMA16(c, a, b0, b1) \
    asm volatile("mma.sync.aligned.m16n8k16.row.col.f32.f16.f16.f32 " \
                 "{%0,%1,%2,%3},{%4,%5,%6,%7},{%8,%9},{%0,%1,%2,%3};" \
                 : "+f"((c)[0]), "+f"((c)[1]), "+f"((c)[2]), "+f"((c)[3]) \
                 : "r"((a)[0]), "r"((a)[1]), "r"((a)[2]), "r"((a)[3]), "r"(b0), "r"(b1))

// event_lengths dtype sniffing (int64 vs int32-demoted)
__device__ __forceinline__ long long get_len(const void* lens, int b) {
    const long long* p64 = (const long long*)lens;
    long long probe = p64[0];
    if (probe >= 1 && probe <= (long long)N_) return p64[b];
    return (long long)((const int*)lens)[b];
}

// Live m-tile counts per batch + batches sorted by descending tile count
// (stable, deterministic). Computed redundantly per thread: ~8 cached loads.
__device__ __forceinline__ void batch_order(const void* lens, int mt[8], int ord[8]) {
    #pragma unroll
    for (int b = 0; b < 8; b++)
        mt[b] = ((int)get_len(lens, b) + 127) >> 7;
    #pragma unroll
    for (int i = 0; i < 8; i++) ord[i] = i;
    #pragma unroll
    for (int i = 1; i < 8; i++) {
        int o = ord[i];
        int j = i;
        while (j > 0 && mt[ord[j - 1]] < mt[o]) { ord[j] = ord[j - 1]; j--; }
        ord[j] = o;
    }
}

// ===========================================================================
// fp16 single-product GEMM machinery — 128x128 tile, 3-stage, 8 warps
// ===========================================================================
__device__ __forceinline__ void load_stage1(
    const __half* __restrict__ Af, int lda,
    const __half* __restrict__ Bf, int ldb,
    int m0, int n0, int k0, uint32_t sbase, int tid)
{
    #pragma unroll
    for (int i = 0; i < 4; i++) {
        int idx = tid + i * 256;
        int r = idx >> 3;
        int c16 = idx & 7;
        uint32_t off = SW128((uint32_t)(r * 128 + c16 * 16));
        CP16(sbase + off,          Af + (size_t)(m0 + r) * lda + k0 + c16 * 8);
        CP16(sbase + OFF_B1 + off, Bf + (size_t)(n0 + r) * ldb + k0 + c16 * 8);
    }
    CP_COMMIT();
}

__device__ __forceinline__ void compute_chunk1(uint32_t sb, int wm, int wn, int lane,
                                               float acc[2][8][4])
{
    const uint32_t rA = sb + (uint32_t)(wm * 32 + (lane & 15)) * 128;
    const uint32_t rB = sb + OFF_B1 + (uint32_t)(wn * 64 + (lane & 15)) * 128;
    const uint32_t xr = (uint32_t)(lane & 7) << 4;
    const uint32_t half_ = (uint32_t)(lane >> 4) << 4;

    #pragma unroll
    for (int ks = 0; ks < 4; ks++) {
        uint32_t c = ((uint32_t)(ks * 32) + half_) ^ xr;
        uint32_t a[2][4], b[8][2];
        #pragma unroll
        for (int ma = 0; ma < 2; ma++)
            LDSM4(a[ma][0], a[ma][1], a[ma][2], a[ma][3], rA + ma * 2048 + c);
        #pragma unroll
        for (int p = 0; p < 4; p++) {
            uint32_t t0, t1, t2, t3;
            LDSM4(t0, t1, t2, t3, rB + p * 2048 + c);
            b[p * 2][0] = t0; b[p * 2 + 1][0] = t1;
            b[p * 2][1] = t2; b[p * 2 + 1][1] = t3;
        }
        #pragma unroll
        for (int ma = 0; ma < 2; ma++)
            #pragma unroll
            for (int na = 0; na < 8; na++)
                MMA16(acc[ma][na], a[ma], b[na][0], b[na][1]);
    }
}

__device__ __forceinline__ void gemm_mainloop1(
    const __half* Af, int lda, const __half* Bf, int ldb,
    int m0, int n0, int nChunks, uint32_t sb, int tid, float acc[2][8][4])
{
    const int lane = tid & 31, wid = tid >> 5;
    const int wm = wid & 3, wn = wid >> 2;

    load_stage1(Af, lda, Bf, ldb, m0, n0, 0, sb, tid);
    if (nChunks > 1)
        load_stage1(Af, lda, Bf, ldb, m0, n0, 64, sb + S1_STAGE, tid);
    for (int c = 0; c < nChunks; c++) {
        if (c + 1 < nChunks) CP_WAIT1(); else CP_WAIT0();
        __syncthreads();
        if (c + 2 < nChunks)
            load_stage1(Af, lda, Bf, ldb, m0, n0, (c + 2) * 64,
                        sb + ((c + 2) % 3) * S1_STAGE, tid);
        compute_chunk1(sb + (c % 3) * S1_STAGE, wm, wn, lane, acc);
    }
}

// ---------------------------------------------------------------------------
// CONVERT+COLSUM: ids 0..8959 = fp16 convert of x and W; ids 8960..9215 =
// colsum(x) partials (fp32, fixed order -> deterministic), 64 rows per CTA.
// ---------------------------------------------------------------------------
__global__ __launch_bounds__(256) void convert_kernel(const float* __restrict__ x,
                                                      const float* __restrict__ Wq,
                                                      const float* __restrict__ Wk,
                                                      const float* __restrict__ Wv) {
    const int id = blockIdx.x;
    const int tid = threadIdx.x;

    if (id >= 8960) {
        int t = id - 8960;            // 0..255
        int b = t >> 5;
        int slab = t & 31;
        const float* xb = x + ((size_t)b * N_ + slab * 64) * D_;
        float s0 = 0.f, s1 = 0.f;
        for (int n = 0; n < 64; n++) {
            s0 += xb[(size_t)n * D_ + tid];
            s1 += xb[(size_t)n * D_ + tid + 256];
        }
        float* o = g_cspart + ((size_t)b * 32 + slab) * D_;
        o[tid] = s0;
        o[tid + 256] = s1;
        return;
    }

    const float* src;
    __half* d;
    size_t i;
    if (id < 8192) {
        src = x; d = g_xf;
        i = (size_t)id * 256 + tid;
    } else {
        int t = id - 8192;
        int z = t >> 8;
        src = (z == 0) ? Wq : (z == 1) ? Wk : Wv;
        d = g_wf + (size_t)z * D_ * D_;
        i = (size_t)(t & 255) * 256 + tid;
    }
    float4 v = ((const float4*)src)[i];
    ((__half2*)d)[i * 2]     = __floats2half2_rn(v.x, v.y);
    ((__half2*)d)[i * 2 + 1] = __floats2half2_rn(v.z, v.w);
}

// ---------------------------------------------------------------------------
// QKV+MEAN: ids 0..7 = colmean matvec; ids 8.. = COMPACTED live projection
// tiles, z interleaved (id%3), sorted-batch-major (longest L first).
// ---------------------------------------------------------------------------
__global__ __launch_bounds__(256, 2) void qkv_mma_kernel(const float* __restrict__ bq,
                                                         const float* __restrict__ bk,
                                                         const float* __restrict__ bv,
                                                         const float* __restrict__ Wv,
                                                         const void* __restrict__ lens) {
    extern __shared__ char dyn[];
    const int tid = threadIdx.x, lane = tid & 31, wid = tid >> 5;
    const int id = blockIdx.x;

    if (id < 8) {
        // colmean via linearity: mean[b] = (colsum(x)/N) @ Wv^T + bv
        const int b = id;
        float* cs = (float*)dyn;       // [512]
        for (int d = tid; d < D_; d += 256) {
            float s = 0.f;
            #pragma unroll
            for (int t = 0; t < 32; t++)
                s += g_cspart[((size_t)b * 32 + t) * D_ + d];
            cs[d] = s;
        }
        __syncthreads();
        for (int dout = wid * 64; dout < wid * 64 + 64; dout++) {
            float s = 0.f;
            for (int k = lane; k < D_; k += 32)
                s += cs[k] * __ldg(Wv + (size_t)dout * D_ + k);
            #pragma unroll
            for (int o = 16; o > 0; o >>= 1)
                s += __shfl_xor_sync(0xffffffffu, s, o);
            if (lane == 0)
                g_mean[(size_t)b * D_ + dout] = s * (1.0f / N_) + __ldg(bv + dout);
        }
        return;
    }

    int mt[8], ord[8];
    batch_order(lens, mt, ord);

    const int s = id - 8;
    const int z = s % 3;
    int u = s / 3;                        // live-tile index within z (sorted)
    int b = -1, mi = 0;
    #pragma unroll
    for (int i = 0; i < 8; i++) {
        int cnt = mt[ord[i]] * 4;
        if (b < 0) {
            if (u < cnt) { b = ord[i]; mi = u >> 2; }
            else u -= cnt;
        }
    }
    if (b < 0) return;
    const int m0 = b * N_ + mi * 128;     // global m; mi*128 < L guaranteed
    const int n0 = (u & 3) * 128;

    uint32_t sb = smem_u32(dyn);
    const int wm = wid & 3, wn = wid >> 2;

    float acc[2][8][4] = {};
    gemm_mainloop1(g_xf, D_, g_wf + (size_t)z * D_ * D_, D_,
                   m0, n0, D_ / 64, sb, tid, acc);

    const float* bias = (z == 0) ? bq : (z == 1) ? bk : bv;

    if (z < 2) {
        __half* o = (z == 0) ? g_qf : g_kf;
        #pragma unroll
        for (int ma = 0; ma < 2; ma++) {
            int m = m0 + wm * 32 + ma * 16 + (lane >> 2);
            #pragma unroll
            for (int na = 0; na < 8; na++) {
                int n = n0 + wn * 64 + na * 8 + (lane & 3) * 2;
                float bv0 = __ldg(bias + n), bv1 = __ldg(bias + n + 1);
                *(__half2*)(o + (size_t)m * D_ + n) =
                    __floats2half2_rn(acc[ma][na][0] + bv0, acc[ma][na][1] + bv1);
                *(__half2*)(o + (size_t)(m + 8) * D_ + n) =
                    __floats2half2_rn(acc[ma][na][2] + bv0, acc[ma][na][3] + bv1);
            }
        }
    } else {
        // V: stage fp32 tile in SMEM, write transposed fp16 [b][d][n]
        __syncthreads();
        float* sf = (float*)dyn;   // [128][129] fp32 = 66KB
        #pragma unroll
        for (int ma = 0; ma < 2; ma++) {
            int r = wm * 32 + ma * 16 + (lane >> 2);
            #pragma unroll
            for (int na = 0; na < 8; na++) {
                int nl = wn * 64 + na * 8 + (lane & 3) * 2;
                float bv0 = __ldg(bias + n0 + nl), bv1 = __ldg(bias + n0 + nl + 1);
                sf[r * 129 + nl]           = acc[ma][na][0] + bv0;
                sf[r * 129 + nl + 1]       = acc[ma][na][1] + bv1;
                sf[(r + 8) * 129 + nl]     = acc[ma][na][2] + bv0;
                sf[(r + 8) * 129 + nl + 1] = acc[ma][na][3] + bv1;
            }
        }
        __syncthreads();
        const int mloc = m0 & 2047;
        int d = tid >> 1;
        int ms = (tid & 1) * 64;
        __half* o = g_vtf + ((size_t)b * D_ + n0 + d) * N_ + mloc + ms;
        #pragma unroll
        for (int c = 0; c < 64; c += 2)
            *(__half2*)(o + c) = __floats2half2_rn(sf[(ms + c) * 129 + d],
                                                   sf[(ms + c + 1) * 129 + d]);
    }
}

// ---------------------------------------------------------------------------
// Scores GEMM: COMPACTED live tiles (sum mt_b^2), sorted longest-first.
// Fused max-free exp, fp16 numerators, per-tile row-sum partials.
// ---------------------------------------------------------------------------
__global__ __launch_bounds__(256, 2) void scores_mma_kernel(const void* __restrict__ lens) {
    int mt[8], ord[8];
    batch_order(lens, mt, ord);

    int s = blockIdx.x;
    int b = -1, mi = 0, ni = 0;
    #pragma unroll
    for (int i = 0; i < 8; i++) {
        int m = mt[ord[i]];
        int cnt = m * m;
        if (b < 0) {
            if (s < cnt) { b = ord[i]; mi = s / m; ni = s - mi * m; }
            else s -= cnt;
        }
    }
    if (b < 0) return;
    const int m0 = mi * 128, n0 = ni * 128;
    const long long L = get_len(lens, b);

    extern __shared__ char dyn[];
    uint32_t sb = smem_u32(dyn);
    const int tid = threadIdx.x, lane = tid & 31, wid = tid >> 5;
    const int wm = wid & 3, wn = wid >> 2;

    float acc[2][8][4] = {};
    const size_t off = (size_t)b * N_ * D_;
    gemm_mainloop1(g_qf + off, D_, g_kf + off, D_, m0, n0, D_ / 64, sb, tid, acc);

    float rsum[2][2] = {};
    #pragma unroll
    for (int ma = 0; ma < 2; ma++) {
        int q0 = m0 + wm * 32 + ma * 16 + (lane >> 2);
        #pragma unroll
        for (int na = 0; na < 8; na++) {
            int kj = n0 + wn * 64 + na * 8 + (lane & 3) * 2;
            bool k0d = (kj >= L), k1d = (kj + 1 >= L);
            #pragma unroll
            for (int h = 0; h < 2; h++) {
                int q = q0 + h * 8;
                bool qd = (q >= L);
                float e0 = (qd || k0d) ? 0.f : __expf(acc[ma][na][h * 2]     * SCALE);
                float e1 = (qd || k1d) ? 0.f : __expf(acc[ma][na][h * 2 + 1] * SCALE);
                __half2 hp = __floats2half2_rn(e0, e1);
                *(__half2*)(g_pf + ((size_t)b * N_ + q) * N_ + kj) = hp;
                float2 fr = __half22float2(hp);   // rounded, for consistent norm
                rsum[ma][h] += fr.x + fr.y;
            }
        }
    }
    __syncthreads();
    float* ps = (float*)dyn;   // [128][2]
    #pragma unroll
    for (int ma = 0; ma < 2; ma++)
        #pragma unroll
        for (int h = 0; h < 2; h++) {
            float v = rsum[ma][h];
            v += __shfl_xor_sync(0xffffffffu, v, 1);
            v += __shfl_xor_sync(0xffffffffu, v, 2);
            if ((lane & 3) == 0) {
                int r = wm * 32 + ma * 16 + (lane >> 2) + h * 8;
                ps[r * 2 + wn] = v;
            }
        }
    __syncthreads();
    if (tid < 128) {
        float t = ps[tid * 2] + ps[tid * 2 + 1];
        g_psum[((size_t)b * 16 + (n0 >> 7)) * N_ + m0 + tid] = t;
    }
}

// ---------------------------------------------------------------------------
// OUT+FILL: ids 0..511 = COMPACTED PV tiles (sorted longest-first, rinv
// in-CTA); ids 512..2559 = fill dead rows (8 rows per CTA).
// ---------------------------------------------------------------------------
__global__ __launch_bounds__(256, 2) void out_fill_kernel(float* __restrict__ Out,
                                                          const void* __restrict__ lens) {
    const int id = blockIdx.x;
    const int tid = threadIdx.x;

    if (id >= 512) {
        int t = id - 512;                  // 0..2047
        int b = t >> 8;
        const long long L = get_len(lens, b);
        int base = (t & 255) * 8;
        int c = tid & 127;
        int r = tid >> 7;                  // 0..1
        float4 v = ((const float4*)(g_mean + (size_t)b * D_))[c];
        #pragma unroll
        for (int i = 0; i < 4; i++) {
            int qi = base + i * 2 + r;
            if (qi >= L)
                ((float4*)(Out + ((size_t)b * N_ + qi) * D_))[c] = v;
        }
        return;
    }

    int mt[8], ord[8];
    batch_order(lens, mt, ord);

    int s = id;
    int b = -1, mi = 0;
    #pragma unroll
    for (int i = 0; i < 8; i++) {
        int cnt = mt[ord[i]] * 4;
        if (b < 0) {
            if (s < cnt) { b = ord[i]; mi = s >> 2; }
            else s -= cnt;
        }
    }
    if (b < 0) return;
    const int m0 = mi * 128;
    const int n0 = (s & 3) * 128;
    const long long L = get_len(lens, b);
    const int nChunks = mt[b] * 2;        // Lpad/64

    extern __shared__ char dyn[];
    uint32_t sb = smem_u32(dyn);
    const int lane = tid & 31, wid = tid >> 5;
    const int wm = wid & 3, wn = wid >> 2;

    float acc[2][8][4] = {};
    gemm_mainloop1(g_pf + (size_t)b * N_ * N_, N_,
                   g_vtf + (size_t)b * D_ * N_, N_,
                   m0, n0, nChunks, sb, tid, acc);

    // In-CTA rinv: sum 16 psum partials per row (fixed order, deterministic)
    __syncthreads();
    float* pr = (float*)dyn;   // [128]
    if (tid < 128) {
        float ssum = 0.f;
        #pragma unroll
        for (int t = 0; t < 16; t++)
            ssum += g_psum[((size_t)b * 16 + t) * N_ + m0 + tid];
        pr[tid] = (ssum > 0.f) ? 1.0f / ssum : 0.f;
    }
    __syncthreads();

    #pragma unroll
    for (int ma = 0; ma < 2; ma++) {
        int r = wm * 32 + ma * 16 + (lane >> 2);
        int m = m0 + r;
        float ri0 = pr[r];
        float ri1 = pr[r + 8];
        float* r0 = Out + ((size_t)b * N_ + m) * D_;
        float* r1 = Out + ((size_t)b * N_ + m + 8) * D_;
        #pragma unroll
        for (int na = 0; na < 8; na++) {
            int n = n0 + wn * 64 + na * 8 + (lane & 3) * 2;
            if (m < L)
                *(float2*)(r0 + n) = make_float2(acc[ma][na][0] * ri0, acc[ma][na][1] * ri0);
            if (m + 8 < L)
                *(float2*)(r1 + n) = make_float2(acc[ma][na][2] * ri1, acc[ma][na][3] * ri1);
        }
    }
}

// ---------------------------------------------------------------------------
extern "C" void kernel_launch(void* const* d_in, const int* in_sizes, int n_in,
                              void* d_out, int out_size)
{
    const float* x    = (const float*)d_in[0];
    const void*  lens = d_in[1];
    const float* Wq   = (const float*)d_in[2];
    const float* bq   = (const float*)d_in[3];
    const float* Wk   = (const float*)d_in[4];
    const float* bk   = (const float*)d_in[5];
    const float* Wv   = (const float*)d_in[6];
    const float* bv   = (const float*)d_in[7];
    float* out = (float*)d_out;

    cudaFuncSetAttribute(qkv_mma_kernel,    cudaFuncAttributeMaxDynamicSharedMemorySize, SMEM_BYTES);
    cudaFuncSetAttribute(scores_mma_kernel, cudaFuncAttributeMaxDynamicSharedMemorySize, SMEM_BYTES);
    cudaFuncSetAttribute(out_fill_kernel,   cudaFuncAttributeMaxDynamicSharedMemorySize, SMEM_BYTES);

    convert_kernel<<<8960 + 256, 256>>>(x, Wq, Wk, Wv);
    qkv_mma_kernel<<<8 + 1536, 256, SMEM_BYTES>>>(bq, bk, bv, Wv, lens);
    scores_mma_kernel<<<2048, 256, SMEM_BYTES>>>(lens);
    out_fill_kernel<<<512 + 2048, 256, SMEM_BYTES>>>(out, lens);
}

// round 15
// speedup vs baseline: 1.0739x; 1.0739x over previous
#include <cuda_runtime.h>
#include <cuda_fp16.h>
#include <cstdint>

// ---------------------------------------------------------------------------
// Problem constants
// ---------------------------------------------------------------------------
constexpr int B_ = 8;
constexpr int N_ = 2048;
constexpr int D_ = 512;
constexpr int M_ = B_ * N_;                    // 16384
constexpr float SCALE = 0.04419417382415922f;  // 1/sqrt(512)

// fp16 GEMM path: CTA tile 128x64, K-chunk 64, 3-stage x 24KB = 72KB,
// 3 CTAs/SM. Stage: A 16KB | B 8KB. Warp tile 32x32 (acc 32 regs).
constexpr int S1_STAGE = 24576;
constexpr int OFF_B1 = 16384;
constexpr int SMEM_BYTES = 3 * S1_STAGE;       // 73728

// ---------------------------------------------------------------------------
// Scratch (static __device__: allocation-guard safe; zero-initialized at load)
// ---------------------------------------------------------------------------
__device__ __align__(256) __half g_xf[(size_t)M_ * D_];          // fp16 x
__device__ __align__(256) __half g_wf[(size_t)3 * D_ * D_];      // fp16 Wq|Wk|Wv
__device__ __align__(256) __half g_qf[(size_t)M_ * D_];          // fp16 q
__device__ __align__(256) __half g_kf[(size_t)M_ * D_];          // fp16 k
__device__ __align__(256) __half g_vtf[(size_t)B_ * D_ * N_];    // fp16 V^T [b][d][n]
__device__ __align__(256) __half g_pf[(size_t)B_ * N_ * N_];     // fp16 exp numerators
__device__ __align__(256) float  g_psum[(size_t)B_ * 32 * N_];   // per-ntile row sums
__device__ __align__(256) float  g_cspart[(size_t)B_ * 32 * D_]; // colsum(x) partials
__device__ __align__(256) float  g_mean[(size_t)B_ * D_];        // colmean(V)

// ---------------------------------------------------------------------------
// Helpers
// ---------------------------------------------------------------------------
__device__ __forceinline__ uint32_t smem_u32(const void* p) {
    uint32_t a;
    asm("{ .reg .u64 t; cvta.to.shared.u64 t, %1; cvt.u32.u64 %0, t; }" : "=r"(a) : "l"(p));
    return a;
}
#define SW128(o) ((o) ^ (((o) >> 3) & 0x70))

#define CP16(dst, src) \
    asm volatile("cp.async.cg.shared.global [%0], [%1], 16;" :: "r"(dst), "l"(src) : "memory")
#define CP_COMMIT() asm volatile("cp.async.commit_group;" ::: "memory")
#define CP_WAIT1() asm volatile("cp.async.wait_group 1;" ::: "memory")
#define CP_WAIT0() asm volatile("cp.async.wait_group 0;" ::: "memory")

#define LDSM4(r0, r1, r2, r3, a) \
    asm volatile("ldmatrix.sync.aligned.m8n8.x4.shared.b16 {%0,%1,%2,%3}, [%4];" \
                 : "=r"(r0), "=r"(r1), "=r"(r2), "=r"(r3) : "r"(a))

#define MMA16(c, a, b0, b1) \
    asm volatile("mma.sync.aligned.m16n8k16.row.col.f32.f16.f16.f32 " \
                 "{%0,%1,%2,%3},{%4,%5,%6,%7},{%8,%9},{%0,%1,%2,%3};" \
                 : "+f"((c)[0]), "+f"((c)[1]), "+f"((c)[2]), "+f"((c)[3]) \
                 : "r"((a)[0]), "r"((a)[1]), "r"((a)[2]), "r"((a)[3]), "r"(b0), "r"(b1))

// event_lengths dtype sniffing (int64 vs int32-demoted)
__device__ __forceinline__ long long get_len(const void* lens, int b) {
    const long long* p64 = (const long long*)lens;
    long long probe = p64[0];
    if (probe >= 1 && probe <= (long long)N_) return p64[b];
    return (long long)((const int*)lens)[b];
}

// ===========================================================================
// fp16 GEMM machinery — CTA 128x64, warp 32x32, 3-stage, 8 warps
// ===========================================================================
__device__ __forceinline__ void load_stage1(
    const __half* __restrict__ Af, int lda,
    const __half* __restrict__ Bf, int ldb,
    int m0, int n0, int k0, uint32_t sbase, int tid)
{
    #pragma unroll
    for (int i = 0; i < 4; i++) {
        int idx = tid + i * 256;        // 0..1023 : A 128 rows x 64 halves
        int r = idx >> 3;
        int c16 = idx & 7;
        uint32_t off = SW128((uint32_t)(r * 128 + c16 * 16));
        CP16(sbase + off, Af + (size_t)(m0 + r) * lda + k0 + c16 * 8);
    }
    #pragma unroll
    for (int i = 0; i < 2; i++) {
        int idx = tid + i * 256;        // 0..511 : B 64 rows x 64 halves
        int r = idx >> 3;
        int c16 = idx & 7;
        uint32_t off = SW128((uint32_t)(r * 128 + c16 * 16));
        CP16(sbase + OFF_B1 + off, Bf + (size_t)(n0 + r) * ldb + k0 + c16 * 8);
    }
    CP_COMMIT();
}

__device__ __forceinline__ void compute_chunk1(uint32_t sb, int wm, int wn, int lane,
                                               float acc[2][4][4])
{
    const uint32_t rA = sb + (uint32_t)(wm * 32 + (lane & 15)) * 128;
    const uint32_t rB = sb + OFF_B1 + (uint32_t)(wn * 32 + (lane & 15)) * 128;
    const uint32_t xr = (uint32_t)(lane & 7) << 4;
    const uint32_t half_ = (uint32_t)(lane >> 4) << 4;

    #pragma unroll
    for (int ks = 0; ks < 4; ks++) {
        uint32_t c = ((uint32_t)(ks * 32) + half_) ^ xr;
        uint32_t a[2][4], b[4][2];
        #pragma unroll
        for (int ma = 0; ma < 2; ma++)
            LDSM4(a[ma][0], a[ma][1], a[ma][2], a[ma][3], rA + ma * 2048 + c);
        #pragma unroll
        for (int p = 0; p < 2; p++) {
            uint32_t t0, t1, t2, t3;
            LDSM4(t0, t1, t2, t3, rB + p * 2048 + c);
            b[p * 2][0] = t0; b[p * 2 + 1][0] = t1;
            b[p * 2][1] = t2; b[p * 2 + 1][1] = t3;
        }
        #pragma unroll
        for (int ma = 0; ma < 2; ma++)
            #pragma unroll
            for (int na = 0; na < 4; na++)
                MMA16(acc[ma][na], a[ma], b[na][0], b[na][1]);
    }
}

__device__ __forceinline__ void gemm_mainloop1(
    const __half* Af, int lda, const __half* Bf, int ldb,
    int m0, int n0, int nChunks, uint32_t sb, int tid, float acc[2][4][4])
{
    const int lane = tid & 31, wid = tid >> 5;
    const int wm = wid & 3, wn = wid >> 2;

    load_stage1(Af, lda, Bf, ldb, m0, n0, 0, sb, tid);
    if (nChunks > 1)
        load_stage1(Af, lda, Bf, ldb, m0, n0, 64, sb + S1_STAGE, tid);
    for (int c = 0; c < nChunks; c++) {
        if (c + 1 < nChunks) CP_WAIT1(); else CP_WAIT0();
        __syncthreads();
        if (c + 2 < nChunks)
            load_stage1(Af, lda, Bf, ldb, m0, n0, (c + 2) * 64,
                        sb + ((c + 2) % 3) * S1_STAGE, tid);
        compute_chunk1(sb + (c % 3) * S1_STAGE, wm, wn, lane, acc);
    }
}

// ---------------------------------------------------------------------------
// CONVERT+COLSUM: ids 0..8959 = fp16 convert of x and W; ids 8960..9215 =
// colsum(x) partials (fp32, fixed order -> deterministic), 64 rows per CTA.
// ---------------------------------------------------------------------------
__global__ __launch_bounds__(256) void convert_kernel(const float* __restrict__ x,
                                                      const float* __restrict__ Wq,
                                                      const float* __restrict__ Wk,
                                                      const float* __restrict__ Wv) {
    const int id = blockIdx.x;
    const int tid = threadIdx.x;

    if (id >= 8960) {
        int t = id - 8960;            // 0..255
        int b = t >> 5;
        int slab = t & 31;
        const float* xb = x + ((size_t)b * N_ + slab * 64) * D_;
        float s0 = 0.f, s1 = 0.f;
        for (int n = 0; n < 64; n++) {
            s0 += xb[(size_t)n * D_ + tid];
            s1 += xb[(size_t)n * D_ + tid + 256];
        }
        float* o = g_cspart + ((size_t)b * 32 + slab) * D_;
        o[tid] = s0;
        o[tid + 256] = s1;
        return;
    }

    const float* src;
    __half* d;
    size_t i;
    if (id < 8192) {
        src = x; d = g_xf;
        i = (size_t)id * 256 + tid;
    } else {
        int t = id - 8192;
        int z = t >> 8;
        src = (z == 0) ? Wq : (z == 1) ? Wk : Wv;
        d = g_wf + (size_t)z * D_ * D_;
        i = (size_t)(t & 255) * 256 + tid;
    }
    float4 v = ((const float4*)src)[i];
    ((__half2*)d)[i * 2]     = __floats2half2_rn(v.x, v.y);
    ((__half2*)d)[i * 2 + 1] = __floats2half2_rn(v.z, v.w);
}

// ---------------------------------------------------------------------------
// QKV+MEAN: ids 0..7 = colmean matvec; ids 8..3079 = projection tiles
// (z = (id-8)>>10, rem 1024 = 128 m-tiles x 8 n-tiles). Dead m-tiles skipped.
// ---------------------------------------------------------------------------
__global__ __launch_bounds__(256, 3) void qkv_mma_kernel(const float* __restrict__ bq,
                                                         const float* __restrict__ bk,
                                                         const float* __restrict__ bv,
                                                         const float* __restrict__ Wv,
                                                         const void* __restrict__ lens) {
    extern __shared__ char dyn[];
    const int tid = threadIdx.x, lane = tid & 31, wid = tid >> 5;
    const int id = blockIdx.x;

    if (id < 8) {
        // colmean via linearity: mean[b] = (colsum(x)/N) @ Wv^T + bv
        const int b = id;
        float* cs = (float*)dyn;       // [512]
        for (int d = tid; d < D_; d += 256) {
            float s = 0.f;
            #pragma unroll
            for (int t = 0; t < 32; t++)
                s += g_cspart[((size_t)b * 32 + t) * D_ + d];
            cs[d] = s;
        }
        __syncthreads();
        for (int dout = wid * 64; dout < wid * 64 + 64; dout++) {
            float s = 0.f;
            for (int k = lane; k < D_; k += 32)
                s += cs[k] * __ldg(Wv + (size_t)dout * D_ + k);
            #pragma unroll
            for (int o = 16; o > 0; o >>= 1)
                s += __shfl_xor_sync(0xffffffffu, s, o);
            if (lane == 0)
                g_mean[(size_t)b * D_ + dout] = s * (1.0f / N_) + __ldg(bv + dout);
        }
        return;
    }

    uint32_t sb = smem_u32(dyn);
    const int wm = wid & 3, wn = wid >> 2;
    const int t = id - 8;
    const int z = t >> 10;                      // 1024 tiles per operand
    const int rem = t & 1023;
    const int m0 = (rem >> 3) * 128, n0 = (rem & 7) * 64;

    const long long L = get_len(lens, m0 >> 11);
    if ((m0 & 2047) >= L) return;

    float acc[2][4][4] = {};
    gemm_mainloop1(g_xf, D_, g_wf + (size_t)z * D_ * D_, D_,
                   m0, n0, D_ / 64, sb, tid, acc);

    const float* bias = (z == 0) ? bq : (z == 1) ? bk : bv;

    if (z < 2) {
        __half* o = (z == 0) ? g_qf : g_kf;
        #pragma unroll
        for (int ma = 0; ma < 2; ma++) {
            int m = m0 + wm * 32 + ma * 16 + (lane >> 2);
            #pragma unroll
            for (int na = 0; na < 4; na++) {
                int n = n0 + wn * 32 + na * 8 + (lane & 3) * 2;
                float bv0 = __ldg(bias + n), bv1 = __ldg(bias + n + 1);
                *(__half2*)(o + (size_t)m * D_ + n) =
                    __floats2half2_rn(acc[ma][na][0] + bv0, acc[ma][na][1] + bv1);
                *(__half2*)(o + (size_t)(m + 8) * D_ + n) =
                    __floats2half2_rn(acc[ma][na][2] + bv0, acc[ma][na][3] + bv1);
            }
        }
    } else {
        // V: stage fp32 tile in SMEM, write transposed fp16 [b][d][n]
        __syncthreads();
        float* sf = (float*)dyn;   // [128][65] fp32 = 33.3KB
        #pragma unroll
        for (int ma = 0; ma < 2; ma++) {
            int r = wm * 32 + ma * 16 + (lane >> 2);
            #pragma unroll
            for (int na = 0; na < 4; na++) {
                int nl = wn * 32 + na * 8 + (lane & 3) * 2;
                float bv0 = __ldg(bias + n0 + nl), bv1 = __ldg(bias + n0 + nl + 1);
                sf[r * 65 + nl]           = acc[ma][na][0] + bv0;
                sf[r * 65 + nl + 1]       = acc[ma][na][1] + bv1;
                sf[(r + 8) * 65 + nl]     = acc[ma][na][2] + bv0;
                sf[(r + 8) * 65 + nl + 1] = acc[ma][na][3] + bv1;
            }
        }
        __syncthreads();
        const int b = m0 >> 11;
        const int mloc = m0 & 2047;
        int d = tid >> 2;                  // 0..63 (local head dim)
        int ms = (tid & 3) * 32;           // m segment
        __half* o = g_vtf + ((size_t)b * D_ + n0 + d) * N_ + mloc + ms;
        #pragma unroll
        for (int c = 0; c < 32; c += 2)
            *(__half2*)(o + c) = __floats2half2_rn(sf[(ms + c) * 65 + d],
                                                   sf[(ms + c + 1) * 65 + d]);
    }
}

// ---------------------------------------------------------------------------
// Scores GEMM (128q x 64k tiles), fused max-free exp, fp16 numerators,
// per-tile row-sum partials. Live tiles only.
// ---------------------------------------------------------------------------
__global__ __launch_bounds__(256, 3) void scores_mma_kernel(const void* __restrict__ lens) {
    const int b = blockIdx.z;
    const int m0 = blockIdx.y * 128, n0 = blockIdx.x * 64;
    const long long L = get_len(lens, b);
    if (m0 >= L || n0 >= L) return;

    extern __shared__ char dyn[];
    uint32_t sb = smem_u32(dyn);
    const int tid = threadIdx.x, lane = tid & 31, wid = tid >> 5;
    const int wm = wid & 3, wn = wid >> 2;

    float acc[2][4][4] = {};
    const size_t off = (size_t)b * N_ * D_;
    gemm_mainloop1(g_qf + off, D_, g_kf + off, D_, m0, n0, D_ / 64, sb, tid, acc);

    float rsum[2][2] = {};
    #pragma unroll
    for (int ma = 0; ma < 2; ma++) {
        int q0 = m0 + wm * 32 + ma * 16 + (lane >> 2);
        #pragma unroll
        for (int na = 0; na < 4; na++) {
            int kj = n0 + wn * 32 + na * 8 + (lane & 3) * 2;
            bool k0d = (kj >= L), k1d = (kj + 1 >= L);
            #pragma unroll
            for (int h = 0; h < 2; h++) {
                int q = q0 + h * 8;
                bool qd = (q >= L);
                float e0 = (qd || k0d) ? 0.f : __expf(acc[ma][na][h * 2]     * SCALE);
                float e1 = (qd || k1d) ? 0.f : __expf(acc[ma][na][h * 2 + 1] * SCALE);
                __half2 hp = __floats2half2_rn(e0, e1);
                *(__half2*)(g_pf + ((size_t)b * N_ + q) * N_ + kj) = hp;
                float2 fr = __half22float2(hp);   // rounded, for consistent norm
                rsum[ma][h] += fr.x + fr.y;
            }
        }
    }
    __syncthreads();
    float* ps = (float*)dyn;   // [128][2]
    #pragma unroll
    for (int ma = 0; ma < 2; ma++)
        #pragma unroll
        for (int h = 0; h < 2; h++) {
            float v = rsum[ma][h];
            v += __shfl_xor_sync(0xffffffffu, v, 1);
            v += __shfl_xor_sync(0xffffffffu, v, 2);
            if ((lane & 3) == 0) {
                int r = wm * 32 + ma * 16 + (lane >> 2) + h * 8;
                ps[r * 2 + wn] = v;
            }
        }
    __syncthreads();
    if (tid < 128) {
        float t = ps[tid * 2] + ps[tid * 2 + 1];
        g_psum[((size_t)b * 32 + (n0 >> 6)) * N_ + m0 + tid] = t;
    }
}

// ---------------------------------------------------------------------------
// OUT+FILL: ids 0..1023 = PV GEMM (128q x 64d tiles, rinv in-CTA from 32
// psum partials, stores pred m<L); ids 1024..9215 = fill dead rows.
// ---------------------------------------------------------------------------
__global__ __launch_bounds__(256, 3) void out_fill_kernel(float* __restrict__ Out,
                                                          const void* __restrict__ lens) {
    const int id = blockIdx.x;
    if (id >= 1024) {
        int t = id - 1024;                 // 0..8191
        int b = t >> 10;
        const long long L = get_len(lens, b);
        int qi = ((t & 1023) << 1) + (threadIdx.x >> 7);
        if (qi < L) return;
        int c = threadIdx.x & 127;
        float4 v = ((const float4*)(g_mean + (size_t)b * D_))[c];
        ((float4*)(Out + ((size_t)b * N_ + qi) * D_))[c] = v;
        return;
    }

    const int b = id >> 7;
    const int rem = id & 127;
    const int m0 = (rem >> 3) * 128, n0 = (rem & 7) * 64;
    const long long L = get_len(lens, b);
    if (m0 >= L) return;
    const int Lpad = ((int)L + 127) & ~127;

    extern __shared__ char dyn[];
    uint32_t sb = smem_u32(dyn);
    const int tid = threadIdx.x, lane = tid & 31, wid = tid >> 5;
    const int wm = wid & 3, wn = wid >> 2;

    float acc[2][4][4] = {};
    gemm_mainloop1(g_pf + (size_t)b * N_ * N_, N_,
                   g_vtf + (size_t)b * D_ * N_, N_,
                   m0, n0, Lpad / 64, sb, tid, acc);

    // In-CTA rinv: sum 32 psum partials per row (fixed order, deterministic)
    __syncthreads();
    float* pr = (float*)dyn;   // [128]
    if (tid < 128) {
        float s = 0.f;
        #pragma unroll
        for (int t = 0; t < 32; t++)
            s += g_psum[((size_t)b * 32 + t) * N_ + m0 + tid];
        pr[tid] = (s > 0.f) ? 1.0f / s : 0.f;
    }
    __syncthreads();

    #pragma unroll
    for (int ma = 0; ma < 2; ma++) {
        int r = wm * 32 + ma * 16 + (lane >> 2);
        int m = m0 + r;
        float ri0 = pr[r];
        float ri1 = pr[r + 8];
        float* r0 = Out + ((size_t)b * N_ + m) * D_;
        float* r1 = Out + ((size_t)b * N_ + m + 8) * D_;
        #pragma unroll
        for (int na = 0; na < 4; na++) {
            int n = n0 + wn * 32 + na * 8 + (lane & 3) * 2;
            if (m < L)
                *(float2*)(r0 + n) = make_float2(acc[ma][na][0] * ri0, acc[ma][na][1] * ri0);
            if (m + 8 < L)
                *(float2*)(r1 + n) = make_float2(acc[ma][na][2] * ri1, acc[ma][na][3] * ri1);
        }
    }
}

// ---------------------------------------------------------------------------
extern "C" void kernel_launch(void* const* d_in, const int* in_sizes, int n_in,
                              void* d_out, int out_size)
{
    const float* x    = (const float*)d_in[0];
    const void*  lens = d_in[1];
    const float* Wq   = (const float*)d_in[2];
    const float* bq   = (const float*)d_in[3];
    const float* Wk   = (const float*)d_in[4];
    const float* bk   = (const float*)d_in[5];
    const float* Wv   = (const float*)d_in[6];
    const float* bv   = (const float*)d_in[7];
    float* out = (float*)d_out;

    cudaFuncSetAttribute(qkv_mma_kernel,    cudaFuncAttributeMaxDynamicSharedMemorySize, SMEM_BYTES);
    cudaFuncSetAttribute(scores_mma_kernel, cudaFuncAttributeMaxDynamicSharedMemorySize, SMEM_BYTES);
    cudaFuncSetAttribute(out_fill_kernel,   cudaFuncAttributeMaxDynamicSharedMemorySize, SMEM_BYTES);

    convert_kernel<<<8960 + 256, 256>>>(x, Wq, Wk, Wv);
    qkv_mma_kernel<<<8 + 3072, 256, SMEM_BYTES>>>(bq, bk, bv, Wv, lens);
    scores_mma_kernel<<<dim3(N_ / 64, N_ / 128, B_), 256, SMEM_BYTES>>>(lens);
    out_fill_kernel<<<1024 + 8192, 256, SMEM_BYTES>>>(out, lens);
}